// round 3
// baseline (speedup 1.0000x reference)
#include <cuda_runtime.h>
#include <cstdint>

#define B 4
#define L 256
#define H 256
#define HS 64
#define NEG_INF (-4294967295.0f)

// Scratch: pre-projected Q (scaled by 1/8), K'' = K + K_time, V'' = V + V_time
__device__ float g_Q[B * L * H];
__device__ float g_K[B * L * H];
__device__ float g_V[B * L * H];

// ---------------------------------------------------------------------------
// Kernel 1: three 1024x256x256 fp32 GEMMs (torch Linear: x @ W^T + b), fused
// epilogues. z = 0: Q (scaled 0.125), z = 1: K + K_time, z = 2: V + V_time.
// ---------------------------------------------------------------------------
__global__ __launch_bounds__(256) void proj_kernel(
    const float* __restrict__ queries, const float* __restrict__ keys,
    const float* __restrict__ Wq, const float* __restrict__ bq,
    const float* __restrict__ Wk, const float* __restrict__ bk,
    const float* __restrict__ Wv, const float* __restrict__ bv,
    const float* __restrict__ K_time, const float* __restrict__ V_time)
{
    const int z = blockIdx.z;
    const float* X    = (z == 0) ? queries : keys;
    const float* W    = (z == 0) ? Wq : (z == 1 ? Wk : Wv);
    const float* bias = (z == 0) ? bq : (z == 1 ? bk : bv);
    const float* add  = (z == 1) ? K_time : (z == 2 ? V_time : nullptr);
    float* out        = (z == 0) ? g_Q : (z == 1 ? g_K : g_V);

    const int rowBase = blockIdx.y * 32;   // gridDim.y = 32 (M = 1024)
    const int colBase = blockIdx.x * 64;   // gridDim.x = 4  (N = 256)

    __shared__ __align__(16) float Xs[16][32];
    __shared__ __align__(16) float Ws[16][64];

    const int t  = threadIdx.x;
    const int tx = t & 15;       // col group (0..15) -> 4 cols each
    const int ty = t >> 4;       // row group (0..15) -> 2 rows each

    float acc[2][4];
#pragma unroll
    for (int i = 0; i < 2; i++)
#pragma unroll
        for (int j = 0; j < 4; j++) acc[i][j] = 0.0f;

    for (int k0 = 0; k0 < 256; k0 += 16) {
#pragma unroll
        for (int e = t; e < 512; e += 256) {
            int row = e >> 4, kk = e & 15;
            Xs[kk][row] = X[(size_t)(rowBase + row) * 256 + k0 + kk];
        }
#pragma unroll
        for (int e = t; e < 1024; e += 256) {
            int c = e >> 4, kk = e & 15;
            Ws[kk][c] = W[(size_t)(colBase + c) * 256 + k0 + kk];
        }
        __syncthreads();
#pragma unroll
        for (int kk = 0; kk < 16; kk++) {
            float a0 = Xs[kk][ty * 2 + 0];
            float a1 = Xs[kk][ty * 2 + 1];
            float4 b4 = *(const float4*)&Ws[kk][tx * 4];
            acc[0][0] += a0 * b4.x; acc[0][1] += a0 * b4.y;
            acc[0][2] += a0 * b4.z; acc[0][3] += a0 * b4.w;
            acc[1][0] += a1 * b4.x; acc[1][1] += a1 * b4.y;
            acc[1][2] += a1 * b4.z; acc[1][3] += a1 * b4.w;
        }
        __syncthreads();
    }

#pragma unroll
    for (int i = 0; i < 2; i++) {
        int row = rowBase + ty * 2 + i;
#pragma unroll
        for (int j = 0; j < 4; j++) {
            int c = colBase + tx * 4 + j;
            float v = acc[i][j] + bias[c];
            if (z == 0)      v *= 0.125f;                       // 1/sqrt(64)
            else             v += add[(size_t)row * 256 + c];
            out[(size_t)row * 256 + c] = v;
        }
    }
}

// ---------------------------------------------------------------------------
// Kernel 2: fused time-aware attention. One CTA per (b, q), 256 threads.
// ---------------------------------------------------------------------------
__global__ __launch_bounds__(256) void attn_kernel(
    const float* __restrict__ tK, const float* __restrict__ tV,
    const int* __restrict__ mask, float* __restrict__ out)
{
    const int b = blockIdx.y;
    const int q = blockIdx.x;
    const int t = threadIdx.x;
    const int ksub = t >> 6;
    const int cg   = t & 63;
    const int lane = t & 31;
    const int n    = cg >> 4;

    __shared__ __align__(16) float sQ[256];
    __shared__ __align__(16) float sS[4][256];
    __shared__ __align__(16) float4 pbuf[4][64];
    __shared__ float red[8];

    const size_t rowQ = (size_t)b * L + q;

    sQ[t] = g_Q[rowQ * 256 + t];
    __syncthreads();
    const float4 q4 = *(const float4*)&sQ[cg * 4];

    // -------- phase 1: scores --------
    const float4* tK4 = (const float4*)tK + rowQ * (L * 64);
    const float4* K4  = (const float4*)g_K + (size_t)b * L * 64;
#pragma unroll 4
    for (int k0 = 0; k0 < L; k0 += 4) {
        int k = k0 + ksub;
        float4 a  = tK4[(size_t)k * 64 + cg];
        float4 kk = K4[(size_t)k * 64 + cg];
        int mk = mask[q * L + k];            // mask is int32 (bool widened)
        float p = q4.x * (a.x + kk.x) + q4.y * (a.y + kk.y)
                + q4.z * (a.z + kk.z) + q4.w * (a.w + kk.w);
        p += __shfl_xor_sync(0xffffffffu, p, 8);
        p += __shfl_xor_sync(0xffffffffu, p, 4);
        p += __shfl_xor_sync(0xffffffffu, p, 2);
        p += __shfl_xor_sync(0xffffffffu, p, 1);
        if ((cg & 15) == 0) {
            sS[n][k] = mk ? NEG_INF : p;
        }
    }
    __syncthreads();

    // -------- phase 2: softmax per head (warp w handles head w>>1, half w&1)
    {
        const int w  = t >> 5;
        const int hn = w >> 1;
        const int kb = (w & 1) * 128 + lane * 4;
        float4 v = *(const float4*)&sS[hn][kb];
        float m = fmaxf(fmaxf(v.x, v.y), fmaxf(v.z, v.w));
#pragma unroll
        for (int o = 16; o; o >>= 1) m = fmaxf(m, __shfl_xor_sync(0xffffffffu, m, o));
        if (lane == 0) red[w] = m;
        __syncthreads();
        const float hm = fmaxf(red[hn * 2], red[hn * 2 + 1]);
        v.x = __expf(v.x - hm); v.y = __expf(v.y - hm);
        v.z = __expf(v.z - hm); v.w = __expf(v.w - hm);
        float s = v.x + v.y + v.z + v.w;
#pragma unroll
        for (int o = 16; o; o >>= 1) s += __shfl_xor_sync(0xffffffffu, s, o);
        __syncthreads();               // all reads of red (max) done
        if (lane == 0) red[w] = s;
        __syncthreads();
        const float inv = 1.0f / (red[hn * 2] + red[hn * 2 + 1]);
        v.x *= inv; v.y *= inv; v.z *= inv; v.w *= inv;
        *(float4*)&sS[hn][kb] = v;
        __syncthreads();
    }

    // -------- phase 3: output --------
    const float4* tV4 = (const float4*)tV + rowQ * (L * 64);
    const float4* V4  = (const float4*)g_V + (size_t)b * L * 64;
    float4 acc = make_float4(0.f, 0.f, 0.f, 0.f);
#pragma unroll 4
    for (int k0 = 0; k0 < L; k0 += 4) {
        int k = k0 + ksub;
        float a = sS[n][k];
        float4 tv = tV4[(size_t)k * 64 + cg];
        float4 vv = V4[(size_t)k * 64 + cg];
        acc.x += a * (tv.x + vv.x);
        acc.y += a * (tv.y + vv.y);
        acc.z += a * (tv.z + vv.z);
        acc.w += a * (tv.w + vv.w);
    }
    pbuf[ksub][cg] = acc;
    __syncthreads();

    // reduce over the 4 ksub partials; pbuf flat float layout: [ksub][c]
    const float* pb = (const float*)pbuf;
    float sum = pb[0 * 256 + t] + pb[1 * 256 + t] + pb[2 * 256 + t] + pb[3 * 256 + t];
    out[rowQ * 256 + t] = sum;
}

extern "C" void kernel_launch(void* const* d_in, const int* in_sizes, int n_in,
                              void* d_out, int out_size)
{
    const float* queries = (const float*)d_in[0];
    const float* keys    = (const float*)d_in[1];
    const int*   mask    = (const int*)d_in[2];
    const float* tK      = (const float*)d_in[3];
    const float* tV      = (const float*)d_in[4];
    const float* K_time  = (const float*)d_in[5];
    const float* V_time  = (const float*)d_in[6];
    const float* Wq = (const float*)d_in[7];
    const float* bq = (const float*)d_in[8];
    const float* Wk = (const float*)d_in[9];
    const float* bk = (const float*)d_in[10];
    const float* Wv = (const float*)d_in[11];
    const float* bv = (const float*)d_in[12];

    proj_kernel<<<dim3(4, 32, 3), 256>>>(queries, keys, Wq, bq, Wk, bk, Wv, bv,
                                         K_time, V_time);
    attn_kernel<<<dim3(L, B), 256>>>(tK, tV, mask, (float*)d_out);
}